// round 13
// baseline (speedup 1.0000x reference)
#include <cuda_runtime.h>

#define LN2  0.69314718055994531f
#define L2E  1.4426950408889634f
typedef unsigned long long ull;

// Transformed warp-uniform weights, single constant struct (one DtoD copy):
//   W1p/B1p pre-scaled by log2(e); W2p pre-scaled by ln2; B2p absorbs -ln2*colsum(W2)
struct CP {
    ull W1p[2][12];   // [n][d*3 + upair]
    ull B1p[2][3];
    ull W2p[2][24];   // [n][u*4 + kpair]
    ull B2p[2][4];
};
__constant__ CP cp;

// scratch: 0..171 = CP floats ; 172..179 = hs0[k] ; 180..187 = ha0[k]
__device__ float d_wscratch[192];

__global__ void prep_kernel(const float* __restrict__ w1, const float* __restrict__ wb1,
                            const float* __restrict__ w2, const float* __restrict__ wb2,
                            const float* __restrict__ Xe,
                            const float* __restrict__ hsw, const float* __restrict__ hsb,
                            const float* __restrict__ haw, const float* __restrict__ hab)
{
    const int t = threadIdx.x;
    if (t < 48) d_wscratch[t]      = w1[t]  * L2E;
    if (t < 12) d_wscratch[48 + t] = wb1[t] * L2E;
    if (t < 96) d_wscratch[60 + t] = w2[t]  * LN2;
    if (t < 16) {
        const int n = t >> 3, k = t & 7;
        float s = 0.f;
        #pragma unroll
        for (int u = 0; u < 6; u++) s += w2[n * 48 + u * 8 + k];
        d_wscratch[156 + t] = wb2[t] - LN2 * s;
    }
    if (t < 16) {
        // interaction-0 h-features are electron/batch independent: x(0) = X[0]
        const int s = t >> 3, k = t & 7;
        const float* W = s ? haw : hsw;   // n=0 block = first 128 floats
        const float* B = s ? hab : hsb;
        float v = B[k];
        #pragma unroll
        for (int d = 0; d < 16; d++) v = fmaf(Xe[d], W[d * 8 + k], v);
        d_wscratch[172 + s * 8 + k] = v;
    }
}

__device__ __forceinline__ ull fma2(ull a, ull b, ull c) {
    ull d; asm("fma.rn.f32x2 %0,%1,%2,%3;" : "=l"(d) : "l"(a), "l"(b), "l"(c)); return d;
}
__device__ __forceinline__ ull mul2(ull a, ull b) {
    ull d; asm("mul.rn.f32x2 %0,%1,%2;" : "=l"(d) : "l"(a), "l"(b)); return d;
}
__device__ __forceinline__ ull add2(ull a, ull b) {
    ull d; asm("add.rn.f32x2 %0,%1,%2;" : "=l"(d) : "l"(a), "l"(b)); return d;
}
__device__ __forceinline__ ull pack2(float lo, float hi) {
    ull d; asm("mov.b64 %0,{%1,%2};" : "=l"(d) : "f"(lo), "f"(hi)); return d;
}
__device__ __forceinline__ void unpack2(ull v, float& lo, float& hi) {
    asm("mov.b64 {%0,%1},%2;" : "=f"(lo), "=f"(hi) : "l"(v));
}
__device__ __forceinline__ ull lds64(const float* p) {
    return *reinterpret_cast<const ull*>(p);
}
// log2(1 + 2^t): EX2 -> FADD -> LG2
__device__ __forceinline__ float lg1p2(float t) {
    float e, r;
    asm("ex2.approx.f32 %0, %1;" : "=f"(e) : "f"(t));
    asm("lg2.approx.f32 %0, %1;" : "=f"(r) : "f"(1.0f + e));
    return r;
}

// pair MLP 4->6(lg-SSP)->8, times spin coef (register array), times self-mask
__device__ __forceinline__ void pair_mlp(int n, const float4& e, const ull* coef,
                                         bool selfj, ull* A)
{
    const ull e0 = pack2(e.x, e.x), e1 = pack2(e.y, e.y),
              e2 = pack2(e.z, e.z), e3 = pack2(e.w, e.w);
    const float mkf = selfj ? 0.f : 1.f;
    const ull m2 = pack2(mkf, mkf);
    float a[6];
    #pragma unroll
    for (int p = 0; p < 3; p++) {
        ull v2 = cp.B1p[n][p];
        v2 = fma2(e0, cp.W1p[n][p],     v2);
        v2 = fma2(e1, cp.W1p[n][3 + p], v2);
        v2 = fma2(e2, cp.W1p[n][6 + p], v2);
        v2 = fma2(e3, cp.W1p[n][9 + p], v2);
        float lo, hi; unpack2(v2, lo, hi);
        a[2 * p] = lg1p2(lo); a[2 * p + 1] = lg1p2(hi);
    }
    #pragma unroll
    for (int q = 0; q < 4; q++) A[q] = cp.B2p[n][q];
    #pragma unroll
    for (int u = 0; u < 6; u++) {
        const ull ad = pack2(a[u], a[u]);
        #pragma unroll
        for (int q = 0; q < 4; q++) A[q] = fma2(ad, cp.W2p[n][u * 4 + q], A[q]);
    }
    #pragma unroll
    for (int q = 0; q < 4; q++) A[q] = mul2(mul2(A[q], coef[q]), m2);
}

__global__ __launch_bounds__(256, 4)
void omni_kernel(const float* __restrict__ dn, const float* __restrict__ de,
                 const float* __restrict__ Xe, const float* __restrict__ Yn,
                 const float* __restrict__ hsw, const float* __restrict__ hsb,
                 const float* __restrict__ haw, const float* __restrict__ hab,
                 const float* __restrict__ gw, const float* __restrict__ gb,
                 const float* __restrict__ orb, float* __restrict__ out)
{
    const int b    = blockIdx.x;
    const int lane = threadIdx.x;        // partner electron j
    const int w    = threadIdx.y;        // warp w owns i = w + 8r, r=0..3
    const int tid  = (w << 5) | lane;
    const unsigned M = 0xffffffffu;

    __shared__ float shwT[2][8][18];     // n=1 only: [s][k][d] pairs (72B stride)
    __shared__ float shb1[2][8];         // n=1 h biases
    __shared__ float sgwT[2][16][10];    // [n][t][k] pairs (40B stride)
    __shared__ float sgb[2][16];
    __shared__ float sY[64];             // [m*8+k]
    __shared__ float sorb[16];
    __shared__ float sx[32][16];         // embeddings
    __shared__ float sc2[2][2][32][10];  // [n][spin][j][k] pairs
    __shared__ float sznuc[2][32][8];
    __shared__ float szr[8][4][8];       // per-warp z buffer [w][r][k]
    __shared__ float spart[8];

    // ---- stage lane-indexed weights ----
    if (tid < 256) {                     // shwT (n=1): [s][k][d] <- (s?haw:hsw)[128 + d*8+k]
        const int s = tid >> 7, r2 = tid & 127, k = r2 >> 4, d = r2 & 15;
        shwT[s][k][d] = (s ? haw : hsw)[128 + d * 8 + k];
    }
    {
        const int n = tid >> 7, r0 = tid & 127, t = r0 >> 3, k = r0 & 7;
        sgwT[n][t][k] = gw[n * 128 + k * 16 + t];
    }
    // sc2[0] from precomputed hs0/ha0 (batch-independent): sc2[0][m][j][k]
    #pragma unroll
    for (int t = tid; t < 512; t += 256) {
        const int m = t >> 8, j = (t >> 3) & 31, k = t & 7;
        sc2[0][m][j][k] = d_wscratch[172 + ((m == (j >> 4)) ? 0 : 8) + k];
    }
    if (tid < 8)  shb1[0][tid] = hsb[8 + tid];
    if (tid < 8)  shb1[1][tid] = hab[8 + tid];
    if (tid < 32) ((float*)sgb)[tid] = gb[tid];
    if (tid < 64) sY[tid]   = Yn[tid];
    if (tid < 16) sorb[tid] = orb[tid];
    #pragma unroll
    for (int t = tid; t < 512; t += 256) sx[t >> 4][t & 15] = Xe[t & 15];

    // lane-permuted r assignment: slot order (KA, SA, KB, SB) = r_sel ^ {0,2,1,3}
    const int r_sel = (lane >> 3) & 3;
    const int rKA = r_sel, rSA = r_sel ^ 2, rKB = r_sel ^ 1, rSB = r_sel ^ 3;
    const int b4f = (lane >> 4) & 1;
    const bool b2 = (lane & 4), b1 = (lane & 2);
    const int q_sel = (lane >> 1) & 3;

    // pair-distance addresses (permuted r-order); ee regs live one interaction only
    const size_t base = ((size_t)b * 32) * 32 + lane;
    const float4* pKA = reinterpret_cast<const float4*>(&de[(base + 32 * (w + 8 * rKA)) << 2]);
    const float4* pSA = reinterpret_cast<const float4*>(&de[(base + 32 * (w + 8 * rSA)) << 2]);
    const float4* pKB = reinterpret_cast<const float4*>(&de[(base + 32 * (w + 8 * rKB)) << 2]);
    const float4* pSB = reinterpret_cast<const float4*>(&de[(base + 32 * (w + 8 * rSB)) << 2]);

    float4 eKA = *pKA, eSA = *pSA, eKB = *pKB, eSB = *pSB;
    __syncthreads();

    // ---- nuclear messages: en loaded once for both interactions ----
    {
        const int ii = tid >> 3, m = tid & 7;
        const float4 en = *reinterpret_cast<const float4*>(
            &dn[(((size_t)b * 32 + ii) * 8 + m) << 2]);
        const ull e0 = pack2(en.x, en.x), e1 = pack2(en.y, en.y),
                  e2 = pack2(en.z, en.z), e3 = pack2(en.w, en.w);
        ull sy[4];
        #pragma unroll
        for (int q = 0; q < 4; q++) sy[q] = lds64(&sY[m * 8 + 2 * q]);
        const bool h4 = (m & 4), h2 = (m & 2);
        const int qc = (m >> 1) & 3;
        #pragma unroll
        for (int n = 0; n < 2; n++) {
            float a[6];
            #pragma unroll
            for (int p = 0; p < 3; p++) {
                ull v2 = cp.B1p[n][p];
                v2 = fma2(e0, cp.W1p[n][p],     v2);
                v2 = fma2(e1, cp.W1p[n][3 + p], v2);
                v2 = fma2(e2, cp.W1p[n][6 + p], v2);
                v2 = fma2(e3, cp.W1p[n][9 + p], v2);
                float lo, hi; unpack2(v2, lo, hi);
                a[2 * p] = lg1p2(lo); a[2 * p + 1] = lg1p2(hi);
            }
            ull A[4];
            #pragma unroll
            for (int q = 0; q < 4; q++) A[q] = cp.B2p[n][q];
            #pragma unroll
            for (int u = 0; u < 6; u++) {
                const ull ad = pack2(a[u], a[u]);
                #pragma unroll
                for (int q = 0; q < 4; q++) A[q] = fma2(ad, cp.W2p[n][u * 4 + q], A[q]);
            }
            #pragma unroll
            for (int q = 0; q < 4; q++) A[q] = mul2(A[q], sy[q]);
            ull s;
            #pragma unroll
            for (int q = 0; q < 2; q++) {
                s = __shfl_xor_sync(M, h4 ? A[q] : A[q + 2], 4);
                A[q] = add2(h4 ? A[q + 2] : A[q], s);
            }
            s = __shfl_xor_sync(M, h2 ? A[0] : A[1], 2);
            A[0] = add2(h2 ? A[1] : A[0], s);
            A[0] = add2(A[0], __shfl_xor_sync(M, A[0], 1));
            if ((m & 1) == 0)
                *reinterpret_cast<ull*>(&sznuc[n][ii][2 * qc]) = A[0];
        }
    }
    __syncthreads();   // covers sznuc, sc2[0], sx, and all weight staging

    const int sH    = (lane >> 3) & 1;
    const int kH    = lane & 7;
    const int rbase = (lane >> 4) << 1;
    const int lt    = lane & 15;

    #pragma unroll
    for (int n = 0; n < 2; n++) {
        if (n == 1) {
            // reload pair distances (L2-warm); issue LDGs before the h-stage work
            eKA = *pKA; eSA = *pSA; eKB = *pKB; eSB = *pSB;

            // ---- h features for interaction 1 (reads own-warp sx, writes sc2[1]) ----
            ull wh[8];
            #pragma unroll
            for (int d2 = 0; d2 < 8; d2++) wh[d2] = lds64(&shwT[sH][kH][2 * d2]);
            const float bb = shb1[sH][kH];
            #pragma unroll
            for (int rr = 0; rr < 2; rr++) {
                const int r = rbase + rr;
                const int i = w + 8 * r;
                ull acc = pack2(bb, 0.f);
                #pragma unroll
                for (int d2 = 0; d2 < 8; d2++)
                    acc = fma2(lds64(&sx[i][2 * d2]), wh[d2], acc);
                float lo, hi; unpack2(acc, lo, hi);
                sc2[1][sH ^ (r >> 1)][i][kH] = lo + hi;
            }
            __syncthreads();
        }

        // hoist coef rows into registers (shared by the two K-slots / two S-slots)
        ull cK[4], cS[4];
        #pragma unroll
        for (int q = 0; q < 4; q++) {
            cK[q] = lds64(&sc2[n][b4f][lane][2 * q]);
            cS[q] = lds64(&sc2[n][1 - b4f][lane][2 * q]);
        }

        // ---- select-free fold rounds 1-2 via permuted slots ----
        ull E[4];
        {
            ull KA[4], SA[4], FA[4];
            pair_mlp(n, eKA, cK, lane == w + 8 * rKA, KA);
            pair_mlp(n, eSA, cS, lane == w + 8 * rSA, SA);
            #pragma unroll
            for (int q = 0; q < 4; q++)
                FA[q] = add2(KA[q], __shfl_xor_sync(M, SA[q], 16));
            ull KB[4], SB[4];
            pair_mlp(n, eKB, cK, lane == w + 8 * rKB, KB);
            pair_mlp(n, eSB, cS, lane == w + 8 * rSB, SB);
            #pragma unroll
            for (int q = 0; q < 4; q++) {
                const ull FB = add2(KB[q], __shfl_xor_sync(M, SB[q], 16));
                E[q] = add2(FA[q], __shfl_xor_sync(M, FB, 8));
            }
        }
        // round 3 (xor4): q-bit1 = b2
        ull G0, G1;
        {
            const ull K0 = b2 ? E[2] : E[0], S0 = b2 ? E[0] : E[2];
            const ull K1 = b2 ? E[3] : E[1], S1 = b2 ? E[1] : E[3];
            G0 = add2(K0, __shfl_xor_sync(M, S0, 4));
            G1 = add2(K1, __shfl_xor_sync(M, S1, 4));
        }
        // round 4 (xor2): q-bit0 = b1 ; round 5 (xor1): butterfly
        ull Z;
        {
            const ull K = b1 ? G1 : G0, S = b1 ? G0 : G1;
            Z = add2(K, __shfl_xor_sync(M, S, 2));
            Z = add2(Z, __shfl_xor_sync(M, Z, 1));
        }
        // add nuclear message, publish z(r_sel, q_sel) to per-warp buffer
        Z = add2(Z, lds64(&sznuc[n][w + 8 * r_sel][2 * q_sel]));
        if ((lane & 1) == 0)
            *reinterpret_cast<ull*>(&szr[w][r_sel][2 * q_sel]) = Z;
        __syncwarp();

        // ---- residual update (g weights loaded late: short live range) ----
        {
            ull gwr[4];
            #pragma unroll
            for (int q = 0; q < 4; q++) gwr[q] = lds64(&sgwT[n][lt][2 * q]);
            const float gbb = sgb[n][lt];
            #pragma unroll
            for (int rr = 0; rr < 2; rr++) {
                const int r = rbase + rr;
                ull d2 = pack2(gbb, 0.f);
                #pragma unroll
                for (int q = 0; q < 4; q++)
                    d2 = fma2(lds64(&szr[w][r][2 * q]), gwr[q], d2);
                float lo, hi; unpack2(d2, lo, hi);
                sx[w + 8 * r][lt] += lo + hi;
            }
        }
        __syncwarp();
    }
    __syncthreads();

    // ---- orbital projection + sum over electrons ----
    float v = 0.f;
    #pragma unroll
    for (int t = tid; t < 512; t += 256)
        v += sx[t >> 4][t & 15] * sorb[t & 15];
    v += __shfl_xor_sync(M, v, 16);
    v += __shfl_xor_sync(M, v, 8);
    v += __shfl_xor_sync(M, v, 4);
    v += __shfl_xor_sync(M, v, 2);
    v += __shfl_xor_sync(M, v, 1);
    if (lane == 0) spart[w] = v;
    __syncthreads();
    if (tid == 0) {
        float s2 = 0.f;
        #pragma unroll
        for (int q = 0; q < 8; q++) s2 += spart[q];
        out[b] = s2;
    }
}

extern "C" void kernel_launch(void* const* d_in, const int* in_sizes, int n_in,
                              void* d_out, int out_size)
{
    const float* dn   = (const float*)d_in[0];
    const float* de   = (const float*)d_in[1];
    const float* Xe   = (const float*)d_in[2];
    const float* Yn   = (const float*)d_in[3];
    const float* hsw  = (const float*)d_in[8];
    const float* hsb  = (const float*)d_in[9];
    const float* haw  = (const float*)d_in[10];
    const float* hab  = (const float*)d_in[11];
    const float* gw   = (const float*)d_in[12];
    const float* gb   = (const float*)d_in[13];
    const float* orb  = (const float*)d_in[14];
    float* out = (float*)d_out;

    // transform pair-MLP weights + n=0 h-features on device, then one DtoD copy
    prep_kernel<<<1, 128>>>((const float*)d_in[4], (const float*)d_in[5],
                            (const float*)d_in[6], (const float*)d_in[7],
                            Xe, hsw, hsb, haw, hab);
    void* scratch = nullptr;
    cudaGetSymbolAddress(&scratch, d_wscratch);
    cudaMemcpyToSymbolAsync(cp, scratch, 172 * sizeof(float), 0, cudaMemcpyDeviceToDevice, 0);

    const int B = in_sizes[0] / (32 * 8 * 4);   // dists_nuc: (B,32,8,4)

    dim3 blk(32, 8);
    omni_kernel<<<B, blk>>>(dn, de, Xe, Yn,
                            hsw, hsb, haw, hab, gw, gb, orb, out);
}

// round 14
// speedup vs baseline: 1.1106x; 1.1106x over previous
#include <cuda_runtime.h>

#define LN2  0.69314718055994531f
#define L2E  1.4426950408889634f
typedef unsigned long long ull;

// Transformed warp-uniform weights (one DtoD copy):
//   W1p/B1p pre-scaled by log2(e); W2p pre-scaled by ln2; B2p absorbs -ln2*colsum(W2)
//   Cc = (X + gb0 + gb1) @ orb  (per-electron constant of the collapsed linear tail)
struct CP {
    ull W1p[2][12];   // [n][d*3 + upair]
    ull B1p[2][3];
    ull W2p[2][24];   // [n][u*4 + kpair]
    ull B2p[2][4];
    float Cc;
    float pad;
};
__constant__ CP cp;

// scratch layout (floats):
//   0..171  CP core | 172 C | 176..183 hs0 | 184..191 ha0
//   192..207 B1[s][k] | 208..335 H1[s][k][k0] | 336..351 v[n][k] (pre-scaled 0.5)
__device__ float d_wscratch[384];

__global__ void prep_kernel(const float* __restrict__ w1, const float* __restrict__ wb1,
                            const float* __restrict__ w2, const float* __restrict__ wb2,
                            const float* __restrict__ Xe,
                            const float* __restrict__ hsw, const float* __restrict__ hsb,
                            const float* __restrict__ haw, const float* __restrict__ hab,
                            const float* __restrict__ gwp, const float* __restrict__ gbp,
                            const float* __restrict__ orb)
{
    const int t = threadIdx.x;
    if (t < 48) d_wscratch[t]      = w1[t]  * L2E;
    if (t < 12) d_wscratch[48 + t] = wb1[t] * L2E;
    if (t < 96) d_wscratch[60 + t] = w2[t]  * LN2;
    if (t < 16) {
        const int n = t >> 3, k = t & 7;
        float s = 0.f;
        #pragma unroll
        for (int u = 0; u < 6; u++) s += w2[n * 48 + u * 8 + k];
        d_wscratch[156 + t] = wb2[t] - LN2 * s;
    }
    if (t < 16) {
        // interaction-0 h-features: x(0) = X[0] uniform
        const int s = t >> 3, k = t & 7;
        const float* W = s ? haw : hsw;
        const float* B = s ? hab : hsb;
        float v = B[k];
        #pragma unroll
        for (int d = 0; d < 16; d++) v = fmaf(Xe[d], W[d * 8 + k], v);
        d_wscratch[176 + s * 8 + k] = v;
    }
    if (t < 16) {
        // B1[s][k] = (X + gb0) @ hw1_s + hb1_s
        const int s = t >> 3, k = t & 7;
        const float* W = (s ? haw : hsw) + 128;
        const float* B = s ? hab : hsb;
        float v = B[8 + k];
        #pragma unroll
        for (int d = 0; d < 16; d++) v = fmaf(Xe[d] + gbp[d], W[d * 8 + k], v);
        d_wscratch[192 + t] = v;
    }
    if (t < 128) {
        // H1[s][k][k0] = sum_d gw0[k0][d] * hw1_s[d][k]
        const int s = t >> 6, k0 = (t >> 3) & 7, k = t & 7;
        const float* W = (s ? haw : hsw) + 128;
        float v = 0.f;
        #pragma unroll
        for (int d = 0; d < 16; d++) v = fmaf(gwp[k0 * 16 + d], W[d * 8 + k], v);
        d_wscratch[208 + s * 64 + k * 8 + k0] = v;
    }
    if (t < 16) {
        // v[n][k] = 0.5 * sum_d g_w[n][k][d] * orb[d]   (0.5: even+odd lanes duplicate Z)
        const int n = t >> 3, k = t & 7;
        float v = 0.f;
        #pragma unroll
        for (int d = 0; d < 16; d++) v = fmaf(gwp[n * 128 + k * 16 + d], orb[d], v);
        d_wscratch[336 + t] = 0.5f * v;
    }
    if (t == 0) {
        float v = 0.f;
        #pragma unroll
        for (int d = 0; d < 16; d++) v = fmaf(Xe[d] + gbp[d] + gbp[16 + d], orb[d], v);
        d_wscratch[172] = v;
    }
}

__device__ __forceinline__ ull fma2(ull a, ull b, ull c) {
    ull d; asm("fma.rn.f32x2 %0,%1,%2,%3;" : "=l"(d) : "l"(a), "l"(b), "l"(c)); return d;
}
__device__ __forceinline__ ull mul2(ull a, ull b) {
    ull d; asm("mul.rn.f32x2 %0,%1,%2;" : "=l"(d) : "l"(a), "l"(b)); return d;
}
__device__ __forceinline__ ull add2(ull a, ull b) {
    ull d; asm("add.rn.f32x2 %0,%1,%2;" : "=l"(d) : "l"(a), "l"(b)); return d;
}
__device__ __forceinline__ ull pack2(float lo, float hi) {
    ull d; asm("mov.b64 %0,{%1,%2};" : "=l"(d) : "f"(lo), "f"(hi)); return d;
}
__device__ __forceinline__ void unpack2(ull v, float& lo, float& hi) {
    asm("mov.b64 {%0,%1},%2;" : "=f"(lo), "=f"(hi) : "l"(v));
}
__device__ __forceinline__ ull lds64(const float* p) {
    return *reinterpret_cast<const ull*>(p);
}
// log2(1 + 2^t): EX2 -> FADD -> LG2
__device__ __forceinline__ float lg1p2(float t) {
    float e, r;
    asm("ex2.approx.f32 %0, %1;" : "=f"(e) : "f"(t));
    asm("lg2.approx.f32 %0, %1;" : "=f"(r) : "f"(1.0f + e));
    return r;
}

// pair MLP 4->6(lg-SSP)->8, times spin coef (register array), times self-mask
__device__ __forceinline__ void pair_mlp(int n, const float4& e, const ull* coef,
                                         bool selfj, ull* A)
{
    const ull e0 = pack2(e.x, e.x), e1 = pack2(e.y, e.y),
              e2 = pack2(e.z, e.z), e3 = pack2(e.w, e.w);
    const float mkf = selfj ? 0.f : 1.f;
    const ull m2 = pack2(mkf, mkf);
    float a[6];
    #pragma unroll
    for (int p = 0; p < 3; p++) {
        ull v2 = cp.B1p[n][p];
        v2 = fma2(e0, cp.W1p[n][p],     v2);
        v2 = fma2(e1, cp.W1p[n][3 + p], v2);
        v2 = fma2(e2, cp.W1p[n][6 + p], v2);
        v2 = fma2(e3, cp.W1p[n][9 + p], v2);
        float lo, hi; unpack2(v2, lo, hi);
        a[2 * p] = lg1p2(lo); a[2 * p + 1] = lg1p2(hi);
    }
    #pragma unroll
    for (int q = 0; q < 4; q++) A[q] = cp.B2p[n][q];
    #pragma unroll
    for (int u = 0; u < 6; u++) {
        const ull ad = pack2(a[u], a[u]);
        #pragma unroll
        for (int q = 0; q < 4; q++) A[q] = fma2(ad, cp.W2p[n][u * 4 + q], A[q]);
    }
    #pragma unroll
    for (int q = 0; q < 4; q++) A[q] = mul2(mul2(A[q], coef[q]), m2);
}

__global__ __launch_bounds__(256, 3)
void omni_kernel(const float* __restrict__ dn, const float* __restrict__ de,
                 const float* __restrict__ Yn, float* __restrict__ out)
{
    const int b    = blockIdx.x;
    const int lane = threadIdx.x;        // partner electron j
    const int w    = threadIdx.y;        // warp w owns i = w + 8r, r=0..3
    const int tid  = (w << 5) | lane;
    const unsigned M = 0xffffffffu;

    __shared__ float sH1[2][8][10];      // [s][k][k0] pairs (40B stride)
    __shared__ float sB1[2][8];
    __shared__ float svp[2][8];          // v[n][k] pre-scaled by 0.5
    __shared__ float sY[64];             // [m*8+k]
    __shared__ float sc2[2][2][32][10];  // [n][spin][j][k] pairs
    __shared__ float sznuc[2][32][8];
    __shared__ float szr[8][4][8];       // per-warp z0 buffer [w][r][k]
    __shared__ float spart[8];

    // ---- stage from prep scratch (L2-resident after first wave) ----
    if (tid < 128) {
        const int s = tid >> 6, kk = (tid >> 3) & 7, k0 = tid & 7;
        sH1[s][kk][k0] = d_wscratch[208 + s * 64 + kk * 8 + k0];
    }
    if (tid < 16) sB1[tid >> 3][tid & 7] = d_wscratch[192 + tid];
    if (tid < 16) svp[tid >> 3][tid & 7] = d_wscratch[336 + tid];
    if (tid < 64) sY[tid] = Yn[tid];
    // sc2[0] from precomputed hs0/ha0 (batch-independent)
    #pragma unroll
    for (int t = tid; t < 512; t += 256) {
        const int m = t >> 8, j = (t >> 3) & 31, k = t & 7;
        sc2[0][m][j][k] = d_wscratch[176 + ((m == (j >> 4)) ? 0 : 8) + k];
    }

    // lane-permuted r assignment: slot order (KA, SA, KB, SB) = r_sel ^ {0,2,1,3}
    const int r_sel = (lane >> 3) & 3;
    const int rKA = r_sel, rSA = r_sel ^ 2, rKB = r_sel ^ 1, rSB = r_sel ^ 3;
    const int b4f = (lane >> 4) & 1;
    const bool b2 = (lane & 4), b1 = (lane & 2);
    const int q_sel = (lane >> 1) & 3;

    // pair distance features, permuted r-order (registers across both interactions)
    float4 eKA, eSA, eKB, eSB;
    {
        const size_t base = ((size_t)b * 32) * 32 + lane;
        eKA = *reinterpret_cast<const float4*>(&de[(base + 32 * (w + 8 * rKA)) << 2]);
        eSA = *reinterpret_cast<const float4*>(&de[(base + 32 * (w + 8 * rSA)) << 2]);
        eKB = *reinterpret_cast<const float4*>(&de[(base + 32 * (w + 8 * rKB)) << 2]);
        eSB = *reinterpret_cast<const float4*>(&de[(base + 32 * (w + 8 * rSB)) << 2]);
    }
    __syncthreads();

    // ---- nuclear messages: en loaded once for both interactions ----
    {
        const int ii = tid >> 3, m = tid & 7;
        const float4 en = *reinterpret_cast<const float4*>(
            &dn[(((size_t)b * 32 + ii) * 8 + m) << 2]);
        const ull e0 = pack2(en.x, en.x), e1 = pack2(en.y, en.y),
                  e2 = pack2(en.z, en.z), e3 = pack2(en.w, en.w);
        ull sy[4];
        #pragma unroll
        for (int q = 0; q < 4; q++) sy[q] = lds64(&sY[m * 8 + 2 * q]);
        const bool h4 = (m & 4), h2 = (m & 2);
        const int qc = (m >> 1) & 3;
        #pragma unroll
        for (int n = 0; n < 2; n++) {
            float a[6];
            #pragma unroll
            for (int p = 0; p < 3; p++) {
                ull v2 = cp.B1p[n][p];
                v2 = fma2(e0, cp.W1p[n][p],     v2);
                v2 = fma2(e1, cp.W1p[n][3 + p], v2);
                v2 = fma2(e2, cp.W1p[n][6 + p], v2);
                v2 = fma2(e3, cp.W1p[n][9 + p], v2);
                float lo, hi; unpack2(v2, lo, hi);
                a[2 * p] = lg1p2(lo); a[2 * p + 1] = lg1p2(hi);
            }
            ull A[4];
            #pragma unroll
            for (int q = 0; q < 4; q++) A[q] = cp.B2p[n][q];
            #pragma unroll
            for (int u = 0; u < 6; u++) {
                const ull ad = pack2(a[u], a[u]);
                #pragma unroll
                for (int q = 0; q < 4; q++) A[q] = fma2(ad, cp.W2p[n][u * 4 + q], A[q]);
            }
            #pragma unroll
            for (int q = 0; q < 4; q++) A[q] = mul2(A[q], sy[q]);
            ull s;
            #pragma unroll
            for (int q = 0; q < 2; q++) {
                s = __shfl_xor_sync(M, h4 ? A[q] : A[q + 2], 4);
                A[q] = add2(h4 ? A[q + 2] : A[q], s);
            }
            s = __shfl_xor_sync(M, h2 ? A[0] : A[1], 2);
            A[0] = add2(h2 ? A[1] : A[0], s);
            A[0] = add2(A[0], __shfl_xor_sync(M, A[0], 1));
            if ((m & 1) == 0)
                *reinterpret_cast<ull*>(&sznuc[n][ii][2 * qc]) = A[0];
        }
    }
    __syncthreads();   // covers sznuc, sc2[0], and staging

    const int sH    = (lane >> 3) & 1;
    const int kH    = lane & 7;
    const int rbase = (lane >> 4) << 1;

    // ===================== interaction 0 =====================
    float pacc;
    {
        ull cK[4], cS[4];
        #pragma unroll
        for (int q = 0; q < 4; q++) {
            cK[q] = lds64(&sc2[0][b4f][lane][2 * q]);
            cS[q] = lds64(&sc2[0][1 - b4f][lane][2 * q]);
        }
        // select-free fold rounds 1-2 via permuted slots
        ull E[4];
        {
            ull KA[4], SA[4], FA[4];
            pair_mlp(0, eKA, cK, lane == w + 8 * rKA, KA);
            pair_mlp(0, eSA, cS, lane == w + 8 * rSA, SA);
            #pragma unroll
            for (int q = 0; q < 4; q++)
                FA[q] = add2(KA[q], __shfl_xor_sync(M, SA[q], 16));
            ull KB[4], SB[4];
            pair_mlp(0, eKB, cK, lane == w + 8 * rKB, KB);
            pair_mlp(0, eSB, cS, lane == w + 8 * rSB, SB);
            #pragma unroll
            for (int q = 0; q < 4; q++) {
                const ull FB = add2(KB[q], __shfl_xor_sync(M, SB[q], 16));
                E[q] = add2(FA[q], __shfl_xor_sync(M, FB, 8));
            }
        }
        ull G0, G1;
        {
            const ull K0 = b2 ? E[2] : E[0], S0 = b2 ? E[0] : E[2];
            const ull K1 = b2 ? E[3] : E[1], S1 = b2 ? E[1] : E[3];
            G0 = add2(K0, __shfl_xor_sync(M, S0, 4));
            G1 = add2(K1, __shfl_xor_sync(M, S1, 4));
        }
        ull Z;
        {
            const ull K = b1 ? G1 : G0, S = b1 ? G0 : G1;
            Z = add2(K, __shfl_xor_sync(M, S, 2));
            Z = add2(Z, __shfl_xor_sync(M, Z, 1));
        }
        Z = add2(Z, lds64(&sznuc[0][w + 8 * r_sel][2 * q_sel]));
        if ((lane & 1) == 0)
            *reinterpret_cast<ull*>(&szr[w][r_sel][2 * q_sel]) = Z;
        // partial output dot: z0 . v0  (v pre-scaled 0.5; all lanes contribute)
        {
            float zl, zh, vl, vh;
            unpack2(Z, zl, zh);
            unpack2(lds64(&svp[0][2 * q_sel]), vl, vh);
            pacc = zl * vl + zh * vh;
        }
        __syncwarp();
    }

    // ---- h features for interaction 1:  c1 = B1 + z0 @ H1  (warp-local szr) ----
    {
        ull h1w[4];
        #pragma unroll
        for (int pq = 0; pq < 4; pq++) h1w[pq] = lds64(&sH1[sH][kH][2 * pq]);
        const float bb = sB1[sH][kH];
        #pragma unroll
        for (int rr = 0; rr < 2; rr++) {
            const int r = rbase + rr;
            const int i = w + 8 * r;
            ull acc = pack2(bb, 0.f);
            #pragma unroll
            for (int pq = 0; pq < 4; pq++)
                acc = fma2(lds64(&szr[w][r][2 * pq]), h1w[pq], acc);
            float lo, hi; unpack2(acc, lo, hi);
            sc2[1][sH ^ (r >> 1)][i][kH] = lo + hi;
        }
    }
    __syncthreads();

    // ===================== interaction 1 =====================
    {
        ull cK[4], cS[4];
        #pragma unroll
        for (int q = 0; q < 4; q++) {
            cK[q] = lds64(&sc2[1][b4f][lane][2 * q]);
            cS[q] = lds64(&sc2[1][1 - b4f][lane][2 * q]);
        }
        ull E[4];
        {
            ull KA[4], SA[4], FA[4];
            pair_mlp(1, eKA, cK, lane == w + 8 * rKA, KA);
            pair_mlp(1, eSA, cS, lane == w + 8 * rSA, SA);
            #pragma unroll
            for (int q = 0; q < 4; q++)
                FA[q] = add2(KA[q], __shfl_xor_sync(M, SA[q], 16));
            ull KB[4], SB[4];
            pair_mlp(1, eKB, cK, lane == w + 8 * rKB, KB);
            pair_mlp(1, eSB, cS, lane == w + 8 * rSB, SB);
            #pragma unroll
            for (int q = 0; q < 4; q++) {
                const ull FB = add2(KB[q], __shfl_xor_sync(M, SB[q], 16));
                E[q] = add2(FA[q], __shfl_xor_sync(M, FB, 8));
            }
        }
        ull G0, G1;
        {
            const ull K0 = b2 ? E[2] : E[0], S0 = b2 ? E[0] : E[2];
            const ull K1 = b2 ? E[3] : E[1], S1 = b2 ? E[1] : E[3];
            G0 = add2(K0, __shfl_xor_sync(M, S0, 4));
            G1 = add2(K1, __shfl_xor_sync(M, S1, 4));
        }
        ull Z;
        {
            const ull K = b1 ? G1 : G0, S = b1 ? G0 : G1;
            Z = add2(K, __shfl_xor_sync(M, S, 2));
            Z = add2(Z, __shfl_xor_sync(M, Z, 1));
        }
        Z = add2(Z, lds64(&sznuc[1][w + 8 * r_sel][2 * q_sel]));
        // partial output dot: z1 . v1  (no publish needed)
        {
            float zl, zh, vl, vh;
            unpack2(Z, zl, zh);
            unpack2(lds64(&svp[1][2 * q_sel]), vl, vh);
            pacc += zl * vl + zh * vh;
        }
    }

    // ---- reduce partial dots: out = 32*C + sum over all lanes/warps ----
    pacc += __shfl_xor_sync(M, pacc, 16);
    pacc += __shfl_xor_sync(M, pacc, 8);
    pacc += __shfl_xor_sync(M, pacc, 4);
    pacc += __shfl_xor_sync(M, pacc, 2);
    pacc += __shfl_xor_sync(M, pacc, 1);
    if (lane == 0) spart[w] = pacc;
    __syncthreads();
    if (tid == 0) {
        float s2 = 32.0f * cp.Cc;
        #pragma unroll
        for (int q = 0; q < 8; q++) s2 += spart[q];
        out[b] = s2;
    }
}

extern "C" void kernel_launch(void* const* d_in, const int* in_sizes, int n_in,
                              void* d_out, int out_size)
{
    const float* dn   = (const float*)d_in[0];
    const float* de   = (const float*)d_in[1];
    const float* Xe   = (const float*)d_in[2];
    const float* Yn   = (const float*)d_in[3];
    const float* hsw  = (const float*)d_in[8];
    const float* hsb  = (const float*)d_in[9];
    const float* haw  = (const float*)d_in[10];
    const float* hab  = (const float*)d_in[11];
    const float* gw   = (const float*)d_in[12];
    const float* gb   = (const float*)d_in[13];
    const float* orb  = (const float*)d_in[14];
    float* out = (float*)d_out;

    // transform weights + collapse the linear tail on device, then one DtoD copy
    prep_kernel<<<1, 128>>>((const float*)d_in[4], (const float*)d_in[5],
                            (const float*)d_in[6], (const float*)d_in[7],
                            Xe, hsw, hsb, haw, hab, gw, gb, orb);
    void* scratch = nullptr;
    cudaGetSymbolAddress(&scratch, d_wscratch);
    cudaMemcpyToSymbolAsync(cp, scratch, 174 * sizeof(float), 0, cudaMemcpyDeviceToDevice, 0);

    const int B = in_sizes[0] / (32 * 8 * 4);   // dists_nuc: (B,32,8,4)

    dim3 blk(32, 8);
    omni_kernel<<<B, blk>>>(dn, de, Yn, out);
}